// round 5
// baseline (speedup 1.0000x reference)
#include <cuda_runtime.h>
#include <cstdint>

// PositionEncoding: out[b,s,d] = x[b,s,d] + pe[s,d]
//   pe[s,d] = sin(s / 10000^(d/D)) if d even else cos(s / 10000^(d/D))
// Shapes: B=8, S=4096, D=1024 (fp32).
//
// R5: persistent one-wave grid (148 SMs x 4 CTAs = 592 CTAs), each CTA
// grid-strides over tiles. Inner body is R2's proven structure: 8
// front-batched ldcg loads (MLP=8), trig overlapped with load latency,
// 8 add+stcg. Removes ~6 wave transitions + per-wave tails of the R2
// multi-wave launch.

static constexpr int B = 8;
static constexpr int S = 4096;
static constexpr int D = 1024;
static constexpr int D4 = D / 4;                  // 256 float4 per row
static constexpr int SD4 = S * D4;                // 1,048,576 float4 positions
static constexpr long long BSTR = (long long)S * D4;   // batch stride (float4)

static constexpr int NSM = 148;
static constexpr int CTAS_PER_SM = 4;
static constexpr int GRID = NSM * CTAS_PER_SM;    // 592 CTAs, one wave
static constexpr int THREADS = 256;

// log2(10000) / D  (D = 1024)
static constexpr float LOG2_10000_OVER_D = 13.287712379549449f / 1024.0f;

__global__ __launch_bounds__(THREADS)
void pe_add_kernel(const float4* __restrict__ x, float4* __restrict__ out) {
    const int stride = GRID * THREADS;

    for (int idx = blockIdx.x * THREADS + threadIdx.x; idx < SD4; idx += stride) {
        // ---- issue all 8 loads first (front-batched LDG.128, MLP=8) ----
        float4 v[B];
#pragma unroll
        for (int b = 0; b < B; b++) {
            v[b] = __ldcg(&x[idx + (long long)b * BSTR]);
        }

        // ---- compute PE while the loads are in flight ----
        int s  = idx >> 8;          // idx / D4
        int d4 = idx & (D4 - 1);    // idx % D4
        int d  = d4 << 2;
        float fs = (float)s;

        float a0 = fs * exp2f(-(float)(d + 0) * LOG2_10000_OVER_D);
        float a1 = fs * exp2f(-(float)(d + 1) * LOG2_10000_OVER_D);
        float a2 = fs * exp2f(-(float)(d + 2) * LOG2_10000_OVER_D);
        float a3 = fs * exp2f(-(float)(d + 3) * LOG2_10000_OVER_D);

        float pex = sinf(a0);   // even dim -> sin
        float pey = cosf(a1);   // odd dim  -> cos
        float pez = sinf(a2);
        float pew = cosf(a3);

        // ---- add + store all 8 ----
#pragma unroll
        for (int b = 0; b < B; b++) {
            float4 o;
            o.x = v[b].x + pex;
            o.y = v[b].y + pey;
            o.z = v[b].z + pez;
            o.w = v[b].w + pew;
            __stcg(&out[idx + (long long)b * BSTR], o);
        }
    }
}

extern "C" void kernel_launch(void* const* d_in, const int* in_sizes, int n_in,
                              void* d_out, int out_size) {
    const float4* x = (const float4*)d_in[0];
    float4* out = (float4*)d_out;

    pe_add_kernel<<<GRID, THREADS>>>(x, out);
}

// round 6
// speedup vs baseline: 1.1332x; 1.1332x over previous
#include <cuda_runtime.h>
#include <cstdint>

// PositionEncoding: out[b,s,d] = x[b,s,d] + pe[s,d]
//   pe[s,d] = sin(s / 10000^(d/D)) if d even else cos(s / 10000^(d/D))
// Shapes: B=8, S=4096, D=1024 (fp32).
//
// R6: R2's proven structure (8 front-batched ldcg loads, trig overlapped,
// 8 add+stcg) with pure 32-bit indexing: total float4 index range is
// 8*1048576 = 8.4M < 2^31, so 64-bit address math (IMAD.WIDE chains +
// register pairs) is pure waste. Cuts regs -> more CTAs/SM and a shorter
// load-issue prologue.

static constexpr int B = 8;
static constexpr int S = 4096;
static constexpr int D = 1024;
static constexpr int D4 = D / 4;                  // 256 float4 per row
static constexpr int SD4 = S * D4;                // 1,048,576
static constexpr int BSTR = S * D4;               // batch stride (float4), fits int

// log2(10000) / D  (D = 1024)
static constexpr float LOG2_10000_OVER_D = 13.287712379549449f / 1024.0f;

__global__ __launch_bounds__(256)
void pe_add_kernel(const float4* __restrict__ x, float4* __restrict__ out) {
    int idx = blockIdx.x * 256 + threadIdx.x;     // grid exactly covers SD4

    // ---- issue all 8 loads first (front-batched LDG.128, MLP=8) ----
    float4 v[B];
#pragma unroll
    for (int b = 0; b < B; b++) {
        v[b] = __ldcg(&x[idx + b * BSTR]);        // 32-bit offsets
    }

    // ---- compute PE while the loads are in flight ----
    int s  = idx >> 8;          // idx / D4
    int d4 = idx & (D4 - 1);    // idx % D4
    int d  = d4 << 2;
    float fs = (float)s;

    float a0 = fs * exp2f(-(float)(d + 0) * LOG2_10000_OVER_D);
    float a1 = fs * exp2f(-(float)(d + 1) * LOG2_10000_OVER_D);
    float a2 = fs * exp2f(-(float)(d + 2) * LOG2_10000_OVER_D);
    float a3 = fs * exp2f(-(float)(d + 3) * LOG2_10000_OVER_D);

    float pex = sinf(a0);   // even dim -> sin
    float pey = cosf(a1);   // odd dim  -> cos
    float pez = sinf(a2);
    float pew = cosf(a3);

    // ---- add + store all 8 ----
#pragma unroll
    for (int b = 0; b < B; b++) {
        float4 o;
        o.x = v[b].x + pex;
        o.y = v[b].y + pey;
        o.z = v[b].z + pez;
        o.w = v[b].w + pew;
        __stcg(&out[idx + b * BSTR], o);
    }
}

extern "C" void kernel_launch(void* const* d_in, const int* in_sizes, int n_in,
                              void* d_out, int out_size) {
    const float4* x = (const float4*)d_in[0];
    float4* out = (float4*)d_out;

    int threads = 256;
    int blocks = SD4 / threads;   // 4096, exact
    pe_add_kernel<<<blocks, threads>>>(x, out);
}